// round 3
// baseline (speedup 1.0000x reference)
#include <cuda_runtime.h>
#include <math.h>
#include <stdint.h>

// Problem constants
constexpr int cB  = 16;
constexpr int cH  = 8;
constexpr int cNL = 256;
constexpr int cNP = 2048;
constexpr int cD  = 64;          // HID
constexpr int cNT = cNL + cNP;   // 2304

// ---------------- scratch (device globals; no runtime allocation) ----------------
__device__ float g_L1 [cB * cH * cNL * cD];         // [bh][l][d]
__device__ float g_L2t[cB * cH * cD * cNL];         // [bh][d][l]
__device__ float g_P1 [cB * cH * cNP * cD];         // [bh][p][d]
__device__ float g_P2t[cB * cH * cD * cNP];         // [bh][d][p]
__device__ float g_att[(size_t)cB * cH * cNL * cNP];// logits, then e = exp(logit - max)
__device__ float g_sinv[cB * cH * cNL];             // 1 / row-sum of e
__device__ float g_l3h[cB * cNL * cH * cD];         // [B, Nl, 512]
__device__ float g_p3h[cB * cNP * cH * cD];         // [B, Np, 512]
__device__ float g_y1l[cB * cNL * cD];
__device__ float g_y1p[cB * cNP * cD];

// ---------------- tf32 helpers ----------------
__device__ __forceinline__ float tf32f(float x) {
    uint32_t u;
    asm("cvt.rna.tf32.f32 %0, %1;" : "=r"(u) : "f"(x));
    return __uint_as_float(u);
}

__device__ __forceinline__ void mma_tf32(float d[4], const uint32_t a[4], const uint32_t b[2]) {
    asm volatile(
        "mma.sync.aligned.m16n8k8.row.col.f32.tf32.tf32.f32 "
        "{%0,%1,%2,%3}, {%4,%5,%6,%7}, {%8,%9}, {%0,%1,%2,%3};\n"
        : "+f"(d[0]), "+f"(d[1]), "+f"(d[2]), "+f"(d[3])
        : "r"(a[0]), "r"(a[1]), "r"(a[2]), "r"(a[3]), "r"(b[0]), "r"(b[1]));
}

// =====================================================================
// Projection (tf32 MMA): out = relu(x @ w[:, h*64:h*64+64] + b), per head.
// which 0 (L1) / 2 (P1): store [bh][n][d].  which 1 (L2t) / 3 (P2t): store [bh][d][n].
// =====================================================================
__global__ __launch_bounds__(256) void proj_mma(const float* __restrict__ x,
                                                const float* __restrict__ w,
                                                const float* __restrict__ bias,
                                                int N, int which) {
    float* out = (which == 0) ? g_L1 : (which == 1) ? g_L2t : (which == 2) ? g_P1 : g_P2t;
    const bool tr = (which == 1) || (which == 3);
    __shared__ float As[64][68];   // [m][k]
    __shared__ float Bs[64][68];   // [n][k]
    const int row0 = blockIdx.x * 64;
    const int h = blockIdx.y;
    const int tid = threadIdx.x;

    for (int i = tid; i < 64 * 64; i += 256) {
        int r = i >> 6, k = i & 63;
        As[r][k] = tf32f(x[(size_t)(row0 + r) * 64 + k]);
    }
    for (int i = tid; i < 64 * 64; i += 256) {
        int k = i >> 6, n = i & 63;
        Bs[n][k] = tf32f(w[(size_t)k * 512 + h * 64 + n]);
    }
    __syncthreads();

    const int wid = tid >> 5, lane = tid & 31, grp = lane >> 2, qid = lane & 3;
    const int m0 = (wid & 3) * 16, n0 = (wid >> 2) * 32;
    float acc[4][4] = {};
#pragma unroll
    for (int kk = 0; kk < 8; kk++) {
        const int k0 = kk * 8;
        uint32_t a[4] = { __float_as_uint(As[m0 + grp][k0 + qid]),
                          __float_as_uint(As[m0 + grp + 8][k0 + qid]),
                          __float_as_uint(As[m0 + grp][k0 + qid + 4]),
                          __float_as_uint(As[m0 + grp + 8][k0 + qid + 4]) };
#pragma unroll
        for (int t = 0; t < 4; t++) {
            uint32_t b[2] = { __float_as_uint(Bs[n0 + t * 8 + grp][k0 + qid]),
                              __float_as_uint(Bs[n0 + t * 8 + grp][k0 + qid + 4]) };
            mma_tf32(acc[t], a, b);
        }
    }

    if (!tr) {
#pragma unroll
        for (int t = 0; t < 4; t++) {
            int c = n0 + t * 8 + 2 * qid;
            float bv0 = bias[h * 64 + c], bv1 = bias[h * 64 + c + 1];
            {
                int row = row0 + m0 + grp;
                int b = row / N, nn = row % N;
                float2 o = make_float2(tf32f(fmaxf(acc[t][0] + bv0, 0.f)),
                                       tf32f(fmaxf(acc[t][1] + bv1, 0.f)));
                *(float2*)&out[(((size_t)b * cH + h) * N + nn) * 64 + c] = o;
            }
            {
                int row = row0 + m0 + grp + 8;
                int b = row / N, nn = row % N;
                float2 o = make_float2(tf32f(fmaxf(acc[t][2] + bv0, 0.f)),
                                       tf32f(fmaxf(acc[t][3] + bv1, 0.f)));
                *(float2*)&out[(((size_t)b * cH + h) * N + nn) * 64 + c] = o;
            }
        }
    } else {
        __syncthreads();
        float (*Ct)[68] = As;   // reuse As as [col d][row]
#pragma unroll
        for (int t = 0; t < 4; t++) {
            int c = n0 + t * 8 + 2 * qid;
            float bv0 = bias[h * 64 + c], bv1 = bias[h * 64 + c + 1];
            int r0l = m0 + grp, r1l = r0l + 8;
            Ct[c][r0l]     = tf32f(fmaxf(acc[t][0] + bv0, 0.f));
            Ct[c + 1][r0l] = tf32f(fmaxf(acc[t][1] + bv1, 0.f));
            Ct[c][r1l]     = tf32f(fmaxf(acc[t][2] + bv0, 0.f));
            Ct[c + 1][r1l] = tf32f(fmaxf(acc[t][3] + bv1, 0.f));
        }
        __syncthreads();
        const int b = row0 / N, nbase = row0 % N;  // 64 | N so one b per block
        for (int i = tid; i < 64 * 64; i += 256) {
            int d = i >> 6, r = i & 63;
            out[(((size_t)b * cH + h) * 64 + d) * N + nbase + r] = Ct[d][r];
        }
    }
}

// =====================================================================
// Energy (tf32 MMA) + fused band mask, NUMERICALLY STABLE two-phase softmax.
// Pass 1: logits -> g_att, track row max. Pass 2: e = exp(logit - max) -> g_att,
// accumulate deterministic row sums -> g_sinv. Block = 64 l, loop p in 64-tiles.
// =====================================================================
__global__ __launch_bounds__(256) void energy_mma(const float* __restrict__ dist) {
    __shared__ float As[64][68];   // L1 tile [l][k]
    __shared__ float Bs[64][68];   // P1 tile [p][k]
    __shared__ float red2[2][64];  // per-half row reductions (max, then sum)
    __shared__ float rowmax[64];
    const int bh = blockIdx.y, b = bh >> 3, h = bh & 7;
    const int l0 = blockIdx.x * 64;
    const int tid = threadIdx.x;
    const int wid = tid >> 5, lane = tid & 31, grp = lane >> 2, qid = lane & 3;
    const int m0 = (wid & 3) * 16, n0 = (wid >> 2) * 32;

    const float* Ap = g_L1 + ((size_t)bh * cNL + l0) * 64;
    for (int i = tid; i < 64 * 64; i += 256) {
        int r = i >> 6, k = i & 63;
        As[r][k] = Ap[(size_t)r * 64 + k];
    }
    __syncthreads();

    // hoist A fragments (A fixed across the whole p loop)
    uint32_t afr[8][4];
#pragma unroll
    for (int kk = 0; kk < 8; kk++) {
        const int k0 = kk * 8;
        afr[kk][0] = __float_as_uint(As[m0 + grp][k0 + qid]);
        afr[kk][1] = __float_as_uint(As[m0 + grp + 8][k0 + qid]);
        afr[kk][2] = __float_as_uint(As[m0 + grp][k0 + qid + 4]);
        afr[kk][3] = __float_as_uint(As[m0 + grp + 8][k0 + qid + 4]);
    }

    const float* Bbase = g_P1 + (size_t)bh * cNP * 64;
    float* ebase = g_att + ((size_t)bh * cNL + l0) * cNP;
    const int lm0 = m0 + grp, lm1 = lm0 + 8;
    const size_t drow0 = ((size_t)(b * cNL) + l0 + lm0) * cNP;
    const size_t drow1 = ((size_t)(b * cNL) + l0 + lm1) * cNP;
    const float hf = (float)h;
    float mx0 = 0.f, mx1 = 0.f;    // masked entries carry logit 0, so max >= 0

    // ---- pass 1: logits + row max ----
    for (int pt = 0; pt < 32; pt++) {
        const int p0 = pt * 64;
        __syncthreads();
        for (int i = tid; i < 64 * 64; i += 256) {
            int p = i >> 6, k = i & 63;
            Bs[p][k] = Bbase[(size_t)(p0 + p) * 64 + k];
        }
        __syncthreads();

        float acc[4][4] = {};
#pragma unroll
        for (int kk = 0; kk < 8; kk++) {
            const int k0 = kk * 8;
#pragma unroll
            for (int t = 0; t < 4; t++) {
                uint32_t bfr[2] = { __float_as_uint(Bs[n0 + t * 8 + grp][k0 + qid]),
                                    __float_as_uint(Bs[n0 + t * 8 + grp][k0 + qid + 4]) };
                mma_tf32(acc[t], afr[kk], bfr);
            }
        }

#pragma unroll
        for (int t = 0; t < 4; t++) {
            const int c = p0 + n0 + t * 8 + 2 * qid;
            const float2 dv0 = *(const float2*)&dist[drow0 + c];
            const float2 dv1 = *(const float2*)&dist[drow1 + c];
            const float dd[4] = {dv0.x, dv0.y, dv1.x, dv1.y};
            float lg[4];
#pragma unroll
            for (int j = 0; j < 4; j++) {
                const float d = dd[j];
                const bool m = (h < 7) ? (d > hf && d <= hf + 3.0f) : (d > 7.0f);
                const float inter = m ? __fdividef(1.0f, d) : 0.0f;
                lg[j] = acc[t][j] * 0.125f * inter;
            }
            mx0 = fmaxf(mx0, fmaxf(lg[0], lg[1]));
            mx1 = fmaxf(mx1, fmaxf(lg[2], lg[3]));
            *(float2*)&ebase[(size_t)lm0 * cNP + c] = make_float2(lg[0], lg[1]);
            *(float2*)&ebase[(size_t)lm1 * cNP + c] = make_float2(lg[2], lg[3]);
        }
    }

    // row-max reduction: over qid (shuffle), then over the two n-halves (smem)
    mx0 = fmaxf(mx0, __shfl_xor_sync(0xffffffffu, mx0, 1));
    mx0 = fmaxf(mx0, __shfl_xor_sync(0xffffffffu, mx0, 2));
    mx1 = fmaxf(mx1, __shfl_xor_sync(0xffffffffu, mx1, 1));
    mx1 = fmaxf(mx1, __shfl_xor_sync(0xffffffffu, mx1, 2));
    if (qid == 0) {
        red2[wid >> 2][lm0] = mx0;
        red2[wid >> 2][lm1] = mx1;
    }
    __syncthreads();
    if (tid < 64) rowmax[tid] = fmaxf(red2[0][tid], red2[1][tid]);
    __syncthreads();
    const float rm0 = rowmax[lm0], rm1 = rowmax[lm1];

    // ---- pass 2: e = exp(logit - rowmax), row sums (re-reads own writes; L2-hot) ----
    float rs0 = 0.f, rs1 = 0.f;
    for (int pt = 0; pt < 32; pt++) {
        const int p0 = pt * 64;
#pragma unroll
        for (int t = 0; t < 4; t++) {
            const int c = p0 + n0 + t * 8 + 2 * qid;
            float2 v0 = *(float2*)&ebase[(size_t)lm0 * cNP + c];
            float2 v1 = *(float2*)&ebase[(size_t)lm1 * cNP + c];
            float e0 = __expf(v0.x - rm0), e1 = __expf(v0.y - rm0);
            float e2 = __expf(v1.x - rm1), e3 = __expf(v1.y - rm1);
            rs0 += e0 + e1;
            rs1 += e2 + e3;
            *(float2*)&ebase[(size_t)lm0 * cNP + c] = make_float2(tf32f(e0), tf32f(e1));
            *(float2*)&ebase[(size_t)lm1 * cNP + c] = make_float2(tf32f(e2), tf32f(e3));
        }
    }

    rs0 += __shfl_xor_sync(0xffffffffu, rs0, 1);
    rs0 += __shfl_xor_sync(0xffffffffu, rs0, 2);
    rs1 += __shfl_xor_sync(0xffffffffu, rs1, 1);
    rs1 += __shfl_xor_sync(0xffffffffu, rs1, 2);
    if (qid == 0) {
        red2[wid >> 2][lm0] = rs0;
        red2[wid >> 2][lm1] = rs1;
    }
    __syncthreads();
    if (tid < 64) {
        g_sinv[bh * cNL + l0 + tid] = 1.0f / (red2[0][tid] + red2[1][tid]);
    }
}

// =====================================================================
// av (tf32 MMA): l3h[b,l,h*64+d] = (sum_p e[l,p] * P2t[d,p]) * sinv[l]
// =====================================================================
__global__ __launch_bounds__(256) void av_mma() {
    __shared__ float As[64][68];   // e tile [l][p]
    __shared__ float Bs[64][68];   // P2t tile [d][p]
    const int bh = blockIdx.y, b = bh >> 3, h = bh & 7;
    const int l0 = blockIdx.x * 64;
    const int tid = threadIdx.x, wid = tid >> 5, lane = tid & 31, grp = lane >> 2, qid = lane & 3;
    const int m0 = (wid & 3) * 16, n0 = (wid >> 2) * 32;
    const float* Ab = g_att + ((size_t)bh * cNL + l0) * cNP;
    const float* Bb = g_P2t + (size_t)bh * 64 * cNP;
    float acc[4][4] = {};

    for (int pt = 0; pt < 32; pt++) {
        const int p0 = pt * 64;
        __syncthreads();
        for (int i = tid; i < 64 * 64; i += 256) {
            int r = i >> 6, k = i & 63;
            As[r][k] = Ab[(size_t)r * cNP + p0 + k];
            Bs[r][k] = Bb[(size_t)r * cNP + p0 + k];
        }
        __syncthreads();
#pragma unroll
        for (int kk = 0; kk < 8; kk++) {
            const int k0 = kk * 8;
            uint32_t a[4] = { __float_as_uint(As[m0 + grp][k0 + qid]),
                              __float_as_uint(As[m0 + grp + 8][k0 + qid]),
                              __float_as_uint(As[m0 + grp][k0 + qid + 4]),
                              __float_as_uint(As[m0 + grp + 8][k0 + qid + 4]) };
#pragma unroll
            for (int t = 0; t < 4; t++) {
                uint32_t bb[2] = { __float_as_uint(Bs[n0 + t * 8 + grp][k0 + qid]),
                                   __float_as_uint(Bs[n0 + t * 8 + grp][k0 + qid + 4]) };
                mma_tf32(acc[t], a, bb);
            }
        }
    }

    const int lm0 = m0 + grp, lm1 = lm0 + 8;
    const float inv0 = g_sinv[bh * cNL + l0 + lm0];
    const float inv1 = g_sinv[bh * cNL + l0 + lm1];
#pragma unroll
    for (int t = 0; t < 4; t++) {
        const int c = n0 + t * 8 + 2 * qid;
        const size_t o0 = ((size_t)(b * cNL) + l0 + lm0) * 512 + h * 64 + c;
        const size_t o1 = ((size_t)(b * cNL) + l0 + lm1) * 512 + h * 64 + c;
        *(float2*)&g_l3h[o0] = make_float2(acc[t][0] * inv0, acc[t][1] * inv0);
        *(float2*)&g_l3h[o1] = make_float2(acc[t][2] * inv1, acc[t][3] * inv1);
    }
}

// =====================================================================
// atv (tf32 MMA): p3h[b,p,h*64+d] = sum_l e[l,p] * (L2t[d,l] * sinv[l])
// =====================================================================
__global__ __launch_bounds__(256) void atv_mma() {
    __shared__ float As[128][33];  // e^T tile [p][l]
    __shared__ float Bs[64][33];   // scaled L2t tile [d][l]
    const int bh = blockIdx.y, b = bh >> 3, h = bh & 7;
    const int p0 = blockIdx.x * 128;
    const int tid = threadIdx.x, wid = tid >> 5, lane = tid & 31, grp = lane >> 2, qid = lane & 3;
    const int m0 = wid * 16;
    const float* eb = g_att + (size_t)bh * cNL * cNP;
    const float* L2b = g_L2t + (size_t)bh * 64 * cNL;
    const float* sv = g_sinv + (size_t)bh * cNL;
    float acc[8][4] = {};

    for (int lt = 0; lt < 8; lt++) {
        const int lb = lt * 32;
        __syncthreads();
        for (int i = tid; i < 32 * 128; i += 256) {
            int r = i >> 7, c = i & 127;     // r = l local, c = p local
            As[c][r] = eb[(size_t)(lb + r) * cNP + p0 + c];
        }
        for (int i = tid; i < 64 * 32; i += 256) {
            int d = i >> 5, k = i & 31;
            Bs[d][k] = tf32f(L2b[(size_t)d * cNL + lb + k] * sv[lb + k]);
        }
        __syncthreads();
#pragma unroll
        for (int kk = 0; kk < 4; kk++) {
            const int k0 = kk * 8;
            uint32_t a[4] = { __float_as_uint(As[m0 + grp][k0 + qid]),
                              __float_as_uint(As[m0 + grp + 8][k0 + qid]),
                              __float_as_uint(As[m0 + grp][k0 + qid + 4]),
                              __float_as_uint(As[m0 + grp + 8][k0 + qid + 4]) };
#pragma unroll
            for (int t = 0; t < 8; t++) {
                uint32_t bb[2] = { __float_as_uint(Bs[t * 8 + grp][k0 + qid]),
                                   __float_as_uint(Bs[t * 8 + grp][k0 + qid + 4]) };
                mma_tf32(acc[t], a, bb);
            }
        }
    }

    const int pm0 = p0 + m0 + grp, pm1 = pm0 + 8;
#pragma unroll
    for (int t = 0; t < 8; t++) {
        const int c = t * 8 + 2 * qid;
        *(float2*)&g_p3h[((size_t)(b * cNP) + pm0) * 512 + h * 64 + c] =
            make_float2(acc[t][0], acc[t][1]);
        *(float2*)&g_p3h[((size_t)(b * cNP) + pm1) * 512 + h * 64 + c] =
            make_float2(acc[t][2], acc[t][3]);
    }
}

// =====================================================================
// fc1 (tf32 MMA): Y[row,d] = X[row,:512] @ W[512,64] + bias
// =====================================================================
__global__ __launch_bounds__(256) void fc1_mma(const float* __restrict__ w,
                                               const float* __restrict__ bias, int which) {
    const float* X = which ? g_p3h : g_l3h;
    float* Y = which ? g_y1p : g_y1l;
    __shared__ float As[64][68];
    __shared__ float Bs[64][68];
    const int row0 = blockIdx.x * 64;
    const int tid = threadIdx.x, wid = tid >> 5, lane = tid & 31, grp = lane >> 2, qid = lane & 3;
    const int m0 = (wid & 3) * 16, n0 = (wid >> 2) * 32;
    float acc[4][4] = {};

    for (int kt = 0; kt < 8; kt++) {
        const int kb = kt * 64;
        __syncthreads();
        for (int i = tid; i < 64 * 64; i += 256) {
            int r = i >> 6, k = i & 63;
            As[r][k] = tf32f(X[(size_t)(row0 + r) * 512 + kb + k]);
        }
        for (int i = tid; i < 64 * 64; i += 256) {
            int k = i >> 6, n = i & 63;
            Bs[n][k] = tf32f(w[(size_t)(kb + k) * 64 + n]);
        }
        __syncthreads();
#pragma unroll
        for (int kk = 0; kk < 8; kk++) {
            const int k0 = kk * 8;
            uint32_t a[4] = { __float_as_uint(As[m0 + grp][k0 + qid]),
                              __float_as_uint(As[m0 + grp + 8][k0 + qid]),
                              __float_as_uint(As[m0 + grp][k0 + qid + 4]),
                              __float_as_uint(As[m0 + grp + 8][k0 + qid + 4]) };
#pragma unroll
            for (int t = 0; t < 4; t++) {
                uint32_t bb[2] = { __float_as_uint(Bs[n0 + t * 8 + grp][k0 + qid]),
                                   __float_as_uint(Bs[n0 + t * 8 + grp][k0 + qid + 4]) };
                mma_tf32(acc[t], a, bb);
            }
        }
    }

    const int r0 = row0 + m0 + grp, r1 = r0 + 8;
#pragma unroll
    for (int t = 0; t < 4; t++) {
        const int c = n0 + t * 8 + 2 * qid;
        const float bv0 = bias[c], bv1 = bias[c + 1];
        *(float2*)&Y[(size_t)r0 * 64 + c] = make_float2(acc[t][0] + bv0, acc[t][1] + bv1);
        *(float2*)&Y[(size_t)r1 * 64 + c] = make_float2(acc[t][2] + bv0, acc[t][3] + bv1);
    }
}

// =====================================================================
// fc2 (fp32, fused concat): out = relu( [Y1, orig] @ W[128,64] + bias )
// =====================================================================
__global__ __launch_bounds__(256) void fc2_kernel(const float* __restrict__ orig,
                                                  const float* __restrict__ w,
                                                  const float* __restrict__ bias,
                                                  float* __restrict__ out,
                                                  int N, int which, int row_off) {
    const float* Y1 = which ? g_y1p : g_y1l;
    __shared__ float As[32][68];
    __shared__ float Bs[32][68];
    const int row0 = blockIdx.x * 64;
    const int tid = threadIdx.x, ty = tid >> 4, tx = tid & 15;
    float acc[4][4] = {};

    for (int k0 = 0; k0 < 128; k0 += 32) {
        const float* src = (k0 < 64) ? Y1 : orig;
        const int kb = k0 & 63;
        for (int i = tid; i < 64 * 32; i += 256) {
            int r = i >> 5, k = i & 31;
            As[k][r] = src[(size_t)(row0 + r) * 64 + kb + k];
        }
        for (int i = tid; i < 32 * 64; i += 256) {
            int k = i >> 6, c = i & 63;
            Bs[k][c] = w[(size_t)(k0 + k) * 64 + c];
        }
        __syncthreads();
#pragma unroll
        for (int k = 0; k < 32; k++) {
            float4 a4 = *(const float4*)&As[k][ty * 4];
            float4 b4 = *(const float4*)&Bs[k][tx * 4];
            float a[4] = {a4.x, a4.y, a4.z, a4.w};
            float bb[4] = {b4.x, b4.y, b4.z, b4.w};
#pragma unroll
            for (int i = 0; i < 4; i++)
#pragma unroll
                for (int j = 0; j < 4; j++) acc[i][j] = fmaf(a[i], bb[j], acc[i][j]);
        }
        __syncthreads();
    }

#pragma unroll
    for (int i = 0; i < 4; i++) {
        int row = row0 + ty * 4 + i;
        int b = row / N, n = row % N;
        float4 o;
        float* op = (float*)&o;
#pragma unroll
        for (int j = 0; j < 4; j++)
            op[j] = fmaxf(acc[i][j] + bias[tx * 4 + j], 0.0f);
        *(float4*)&out[((size_t)b * cNT + row_off + n) * 64 + tx * 4] = o;
    }
}

// =====================================================================
extern "C" void kernel_launch(void* const* d_in, const int* in_sizes, int n_in,
                              void* d_out, int out_size) {
    (void)in_sizes; (void)n_in; (void)out_size;
    const float* ligand = (const float*)d_in[0];
    const float* prot   = (const float*)d_in[1];
    const float* dist   = (const float*)d_in[2];
    const float* w_l1 = (const float*)d_in[3];
    const float* b_l1 = (const float*)d_in[4];
    const float* w_l2 = (const float*)d_in[5];
    const float* b_l2 = (const float*)d_in[6];
    const float* w_p1 = (const float*)d_in[7];
    const float* b_p1 = (const float*)d_in[8];
    const float* w_p2 = (const float*)d_in[9];
    const float* b_p2 = (const float*)d_in[10];
    const float* fc11_w = (const float*)d_in[11];
    const float* fc11_b = (const float*)d_in[12];
    const float* fc12_w = (const float*)d_in[13];
    const float* fc12_b = (const float*)d_in[14];
    const float* fc21_w = (const float*)d_in[15];
    const float* fc21_b = (const float*)d_in[16];
    const float* fc22_w = (const float*)d_in[17];
    const float* fc22_b = (const float*)d_in[18];
    float* out = (float*)d_out;

    // Projections (tf32). L1/P1 natural layout; L2/P2 transposed [d][n].
    proj_mma<<<dim3(cB * cNL / 64, cH), 256>>>(ligand, w_l1, b_l1, cNL, 0);
    proj_mma<<<dim3(cB * cNL / 64, cH), 256>>>(ligand, w_l2, b_l2, cNL, 1);
    proj_mma<<<dim3(cB * cNP / 64, cH), 256>>>(prot, w_p1, b_p1, cNP, 2);
    proj_mma<<<dim3(cB * cNP / 64, cH), 256>>>(prot, w_p2, b_p2, cNP, 3);

    // Fused energy + mask + stable softmax (logits pass + exp/sum pass, one launch)
    energy_mma<<<dim3(cNL / 64, cB * cH), 256>>>(dist);

    // Attention GEMMs with normalization folded in
    av_mma<<<dim3(cNL / 64, cB * cH), 256>>>();
    atv_mma<<<dim3(cNP / 128, cB * cH), 256>>>();

    // FC heads
    fc1_mma<<<cB * cNL / 64, 256>>>(fc11_w, fc11_b, 0);
    fc1_mma<<<cB * cNP / 64, 256>>>(fc21_w, fc21_b, 1);
    fc2_kernel<<<cB * cNL / 64, 256>>>(ligand, fc12_w, fc12_b, out, cNL, 0, 0);
    fc2_kernel<<<cB * cNP / 64, 256>>>(prot, fc22_w, fc22_b, out, cNP, 1, cNL);
}

// round 4
// speedup vs baseline: 1.4008x; 1.4008x over previous
#include <cuda_runtime.h>
#include <math.h>
#include <stdint.h>

// Problem constants
constexpr int cB  = 16;
constexpr int cH  = 8;
constexpr int cNL = 256;
constexpr int cNP = 2048;
constexpr int cD  = 64;          // HID
constexpr int cNT = cNL + cNP;   // 2304

// ---------------- scratch (device globals; no runtime allocation) ----------------
__device__ float g_L1 [cB * cH * cNL * cD];         // [bh][l][d]
__device__ float g_L2t[cB * cH * cD * cNL];         // [bh][d][l]
__device__ float g_P1 [cB * cH * cNP * cD];         // [bh][p][d]
__device__ float g_P2t[cB * cH * cD * cNP];         // [bh][d][p]
__device__ float g_att[(size_t)cB * cH * cNL * cNP];// e = exp(logit - rowmax), tf32
__device__ float g_sinv[cB * cH * cNL];             // 1 / row-sum of e
__device__ float g_l3h[cB * cNL * cH * cD];         // [B, Nl, 512]
__device__ float g_p3h[cB * cNP * cH * cD];         // [B, Np, 512]
__device__ float g_y1l[cB * cNL * cD];
__device__ float g_y1p[cB * cNP * cD];

// ---------------- tf32 helpers ----------------
__device__ __forceinline__ float tf32f(float x) {
    uint32_t u;
    asm("cvt.rna.tf32.f32 %0, %1;" : "=r"(u) : "f"(x));
    return __uint_as_float(u);
}

__device__ __forceinline__ void mma_tf32(float d[4], const uint32_t a[4], const uint32_t b[2]) {
    asm volatile(
        "mma.sync.aligned.m16n8k8.row.col.f32.tf32.tf32.f32 "
        "{%0,%1,%2,%3}, {%4,%5,%6,%7}, {%8,%9}, {%0,%1,%2,%3};\n"
        : "+f"(d[0]), "+f"(d[1]), "+f"(d[2]), "+f"(d[3])
        : "r"(a[0]), "r"(a[1]), "r"(a[2]), "r"(a[3]), "r"(b[0]), "r"(b[1]));
}

// =====================================================================
// Projection (tf32 MMA): out = relu(x @ w[:, h*64:h*64+64] + b), per head.
// which 0 (L1) / 2 (P1): store [bh][n][d].  which 1 (L2t) / 3 (P2t): store [bh][d][n].
// Epilogues staged through smem for coalesced float4 global writes.
// =====================================================================
__global__ __launch_bounds__(256) void proj_mma(const float* __restrict__ x,
                                                const float* __restrict__ w,
                                                const float* __restrict__ bias,
                                                int N, int which) {
    float* out = (which == 0) ? g_L1 : (which == 1) ? g_L2t : (which == 2) ? g_P1 : g_P2t;
    const bool tr = (which == 1) || (which == 3);
    __shared__ float As[64][68];   // [m][k], reused as C stage
    __shared__ float Bs[64][68];   // [n][k]
    const int row0 = blockIdx.x * 64;
    const int h = blockIdx.y;
    const int tid = threadIdx.x;

    for (int i = tid; i < 64 * 64; i += 256) {
        int r = i >> 6, k = i & 63;
        As[r][k] = tf32f(x[(size_t)(row0 + r) * 64 + k]);
    }
    for (int i = tid; i < 64 * 64; i += 256) {
        int k = i >> 6, n = i & 63;
        Bs[n][k] = tf32f(w[(size_t)k * 512 + h * 64 + n]);
    }
    __syncthreads();

    const int wid = tid >> 5, lane = tid & 31, grp = lane >> 2, qid = lane & 3;
    const int m0 = (wid & 3) * 16, n0 = (wid >> 2) * 32;
    float acc[4][4] = {};
#pragma unroll
    for (int kk = 0; kk < 8; kk++) {
        const int k0 = kk * 8;
        uint32_t a[4] = { __float_as_uint(As[m0 + grp][k0 + qid]),
                          __float_as_uint(As[m0 + grp + 8][k0 + qid]),
                          __float_as_uint(As[m0 + grp][k0 + qid + 4]),
                          __float_as_uint(As[m0 + grp + 8][k0 + qid + 4]) };
#pragma unroll
        for (int t = 0; t < 4; t++) {
            uint32_t b[2] = { __float_as_uint(Bs[n0 + t * 8 + grp][k0 + qid]),
                              __float_as_uint(Bs[n0 + t * 8 + grp][k0 + qid + 4]) };
            mma_tf32(acc[t], a, b);
        }
    }
    __syncthreads();

    if (!tr) {
        // stage as [row][col], then coalesced row writes
#pragma unroll
        for (int t = 0; t < 4; t++) {
            int c = n0 + t * 8 + 2 * qid;
            float bv0 = bias[h * 64 + c], bv1 = bias[h * 64 + c + 1];
            int r0l = m0 + grp, r1l = r0l + 8;
            As[r0l][c]     = tf32f(fmaxf(acc[t][0] + bv0, 0.f));
            As[r0l][c + 1] = tf32f(fmaxf(acc[t][1] + bv1, 0.f));
            As[r1l][c]     = tf32f(fmaxf(acc[t][2] + bv0, 0.f));
            As[r1l][c + 1] = tf32f(fmaxf(acc[t][3] + bv1, 0.f));
        }
        __syncthreads();
        const int b = row0 / N, nbase = row0 % N;  // 64 | N so one b per block
        for (int i = tid; i < 1024; i += 256) {
            int r = i >> 4, c4 = (i & 15) * 4;
            *(float4*)&out[(((size_t)b * cH + h) * N + nbase + r) * 64 + c4] =
                *(float4*)&As[r][c4];
        }
    } else {
        // stage transposed as [col d][row], then coalesced row writes along n
#pragma unroll
        for (int t = 0; t < 4; t++) {
            int c = n0 + t * 8 + 2 * qid;
            float bv0 = bias[h * 64 + c], bv1 = bias[h * 64 + c + 1];
            int r0l = m0 + grp, r1l = r0l + 8;
            As[c][r0l]     = tf32f(fmaxf(acc[t][0] + bv0, 0.f));
            As[c + 1][r0l] = tf32f(fmaxf(acc[t][1] + bv1, 0.f));
            As[c][r1l]     = tf32f(fmaxf(acc[t][2] + bv0, 0.f));
            As[c + 1][r1l] = tf32f(fmaxf(acc[t][3] + bv1, 0.f));
        }
        __syncthreads();
        const int b = row0 / N, nbase = row0 % N;
        for (int i = tid; i < 1024; i += 256) {
            int d = i >> 4, r4 = (i & 15) * 4;
            *(float4*)&out[(((size_t)b * cH + h) * 64 + d) * N + nbase + r4] =
                *(float4*)&As[d][r4];
        }
    }
}

// =====================================================================
// Energy (tf32 MMA) + band mask + stable softmax numerator, single launch:
//   pass 1: MMA -> logits -> row max only (nothing written)
//   pass 2: recompute MMA -> e = exp(logit - max) -> smem stage -> coalesced
//           float4 writes to g_att; deterministic row sums -> g_sinv.
// =====================================================================
__global__ __launch_bounds__(256) void energy_mma(const float* __restrict__ dist) {
    __shared__ float As[64][68];   // L1 tile [l][k]
    __shared__ float Bs[64][68];   // P1 tile [p][k]; reused as e stage [l][p]
    __shared__ float red2[2][64];
    __shared__ float rowmax_s[64];
    const int bh = blockIdx.y, b = bh >> 3, h = bh & 7;
    const int l0 = blockIdx.x * 64;
    const int tid = threadIdx.x;
    const int wid = tid >> 5, lane = tid & 31, grp = lane >> 2, qid = lane & 3;
    const int m0 = (wid & 3) * 16, n0 = (wid >> 2) * 32;

    const float* Ap = g_L1 + ((size_t)bh * cNL + l0) * 64;
    for (int i = tid; i < 64 * 64; i += 256) {
        int r = i >> 6, k = i & 63;
        As[r][k] = Ap[(size_t)r * 64 + k];
    }
    __syncthreads();

    uint32_t afr[8][4];
#pragma unroll
    for (int kk = 0; kk < 8; kk++) {
        const int k0 = kk * 8;
        afr[kk][0] = __float_as_uint(As[m0 + grp][k0 + qid]);
        afr[kk][1] = __float_as_uint(As[m0 + grp + 8][k0 + qid]);
        afr[kk][2] = __float_as_uint(As[m0 + grp][k0 + qid + 4]);
        afr[kk][3] = __float_as_uint(As[m0 + grp + 8][k0 + qid + 4]);
    }

    const float* Bbase = g_P1 + (size_t)bh * cNP * 64;
    float* ebase = g_att + ((size_t)bh * cNL + l0) * cNP;
    const int lm0 = m0 + grp, lm1 = lm0 + 8;
    const size_t drow0 = ((size_t)(b * cNL) + l0 + lm0) * cNP;
    const size_t drow1 = ((size_t)(b * cNL) + l0 + lm1) * cNP;
    const float hf = (float)h;

    // ---- pass 1: row max only ----
    float mx0 = 0.f, mx1 = 0.f;    // masked entries carry logit 0
    for (int pt = 0; pt < 32; pt++) {
        const int p0 = pt * 64;
        __syncthreads();
        for (int i = tid; i < 64 * 64; i += 256) {
            int p = i >> 6, k = i & 63;
            Bs[p][k] = Bbase[(size_t)(p0 + p) * 64 + k];
        }
        __syncthreads();

        float acc[4][4] = {};
#pragma unroll
        for (int kk = 0; kk < 8; kk++) {
            const int k0 = kk * 8;
#pragma unroll
            for (int t = 0; t < 4; t++) {
                uint32_t bfr[2] = { __float_as_uint(Bs[n0 + t * 8 + grp][k0 + qid]),
                                    __float_as_uint(Bs[n0 + t * 8 + grp][k0 + qid + 4]) };
                mma_tf32(acc[t], afr[kk], bfr);
            }
        }

#pragma unroll
        for (int t = 0; t < 4; t++) {
            const int c = p0 + n0 + t * 8 + 2 * qid;
            const float2 dv0 = *(const float2*)&dist[drow0 + c];
            const float2 dv1 = *(const float2*)&dist[drow1 + c];
            const float dd[4] = {dv0.x, dv0.y, dv1.x, dv1.y};
#pragma unroll
            for (int j = 0; j < 4; j++) {
                const float d = dd[j];
                const bool m = (h < 7) ? (d > hf && d <= hf + 3.0f) : (d > 7.0f);
                const float inter = m ? __fdividef(1.0f, d) : 0.0f;
                const float lg = acc[t][j] * 0.125f * inter;
                if (j < 2) mx0 = fmaxf(mx0, lg); else mx1 = fmaxf(mx1, lg);
            }
        }
    }

    mx0 = fmaxf(mx0, __shfl_xor_sync(0xffffffffu, mx0, 1));
    mx0 = fmaxf(mx0, __shfl_xor_sync(0xffffffffu, mx0, 2));
    mx1 = fmaxf(mx1, __shfl_xor_sync(0xffffffffu, mx1, 1));
    mx1 = fmaxf(mx1, __shfl_xor_sync(0xffffffffu, mx1, 2));
    if (qid == 0) {
        red2[wid >> 2][lm0] = mx0;
        red2[wid >> 2][lm1] = mx1;
    }
    __syncthreads();
    if (tid < 64) rowmax_s[tid] = fmaxf(red2[0][tid], red2[1][tid]);
    __syncthreads();
    const float rm0 = rowmax_s[lm0], rm1 = rowmax_s[lm1];

    // ---- pass 2: recompute, e = exp(lg - rm), staged coalesced writes, sums ----
    float rs0 = 0.f, rs1 = 0.f;
    for (int pt = 0; pt < 32; pt++) {
        const int p0 = pt * 64;
        __syncthreads();
        for (int i = tid; i < 64 * 64; i += 256) {
            int p = i >> 6, k = i & 63;
            Bs[p][k] = Bbase[(size_t)(p0 + p) * 64 + k];
        }
        __syncthreads();

        float acc[4][4] = {};
#pragma unroll
        for (int kk = 0; kk < 8; kk++) {
            const int k0 = kk * 8;
#pragma unroll
            for (int t = 0; t < 4; t++) {
                uint32_t bfr[2] = { __float_as_uint(Bs[n0 + t * 8 + grp][k0 + qid]),
                                    __float_as_uint(Bs[n0 + t * 8 + grp][k0 + qid + 4]) };
                mma_tf32(acc[t], afr[kk], bfr);
            }
        }

        float ev[4][4];
#pragma unroll
        for (int t = 0; t < 4; t++) {
            const int c = p0 + n0 + t * 8 + 2 * qid;
            const float2 dv0 = *(const float2*)&dist[drow0 + c];
            const float2 dv1 = *(const float2*)&dist[drow1 + c];
            const float dd[4] = {dv0.x, dv0.y, dv1.x, dv1.y};
#pragma unroll
            for (int j = 0; j < 4; j++) {
                const float d = dd[j];
                const bool m = (h < 7) ? (d > hf && d <= hf + 3.0f) : (d > 7.0f);
                const float inter = m ? __fdividef(1.0f, d) : 0.0f;
                const float lg = acc[t][j] * 0.125f * inter;
                ev[t][j] = __expf(lg - (j < 2 ? rm0 : rm1));
            }
            rs0 += ev[t][0] + ev[t][1];
            rs1 += ev[t][2] + ev[t][3];
        }

        __syncthreads();   // done reading Bs as P1 tile
#pragma unroll
        for (int t = 0; t < 4; t++) {
            const int cl = n0 + t * 8 + 2 * qid;
            Bs[lm0][cl]     = tf32f(ev[t][0]);
            Bs[lm0][cl + 1] = tf32f(ev[t][1]);
            Bs[lm1][cl]     = tf32f(ev[t][2]);
            Bs[lm1][cl + 1] = tf32f(ev[t][3]);
        }
        __syncthreads();
        for (int i = tid; i < 1024; i += 256) {
            int l = i >> 4, c4 = (i & 15) * 4;
            *(float4*)&ebase[(size_t)l * cNP + p0 + c4] = *(float4*)&Bs[l][c4];
        }
    }

    rs0 += __shfl_xor_sync(0xffffffffu, rs0, 1);
    rs0 += __shfl_xor_sync(0xffffffffu, rs0, 2);
    rs1 += __shfl_xor_sync(0xffffffffu, rs1, 1);
    rs1 += __shfl_xor_sync(0xffffffffu, rs1, 2);
    if (qid == 0) {
        red2[wid >> 2][lm0] = rs0;
        red2[wid >> 2][lm1] = rs1;
    }
    __syncthreads();
    if (tid < 64) {
        g_sinv[bh * cNL + l0 + tid] = 1.0f / (red2[0][tid] + red2[1][tid]);
    }
}

// =====================================================================
// av (tf32 MMA): l3h[b,l,h*64+d] = (sum_p e[l,p] * P2t[d,p]) * sinv[l]
// Staged coalesced epilogue.
// =====================================================================
__global__ __launch_bounds__(256) void av_mma() {
    __shared__ float As[64][68];   // e tile [l][p]; reused as C stage [l][d]
    __shared__ float Bs[64][68];   // P2t tile [d][p]
    const int bh = blockIdx.y, b = bh >> 3, h = bh & 7;
    const int l0 = blockIdx.x * 64;
    const int tid = threadIdx.x, wid = tid >> 5, lane = tid & 31, grp = lane >> 2, qid = lane & 3;
    const int m0 = (wid & 3) * 16, n0 = (wid >> 2) * 32;
    const float* Ab = g_att + ((size_t)bh * cNL + l0) * cNP;
    const float* Bb = g_P2t + (size_t)bh * 64 * cNP;
    float acc[4][4] = {};

    for (int pt = 0; pt < 32; pt++) {
        const int p0 = pt * 64;
        __syncthreads();
        for (int i = tid; i < 64 * 64; i += 256) {
            int r = i >> 6, k = i & 63;
            As[r][k] = Ab[(size_t)r * cNP + p0 + k];
            Bs[r][k] = Bb[(size_t)r * cNP + p0 + k];
        }
        __syncthreads();
#pragma unroll
        for (int kk = 0; kk < 8; kk++) {
            const int k0 = kk * 8;
            uint32_t a[4] = { __float_as_uint(As[m0 + grp][k0 + qid]),
                              __float_as_uint(As[m0 + grp + 8][k0 + qid]),
                              __float_as_uint(As[m0 + grp][k0 + qid + 4]),
                              __float_as_uint(As[m0 + grp + 8][k0 + qid + 4]) };
#pragma unroll
            for (int t = 0; t < 4; t++) {
                uint32_t bb[2] = { __float_as_uint(Bs[n0 + t * 8 + grp][k0 + qid]),
                                   __float_as_uint(Bs[n0 + t * 8 + grp][k0 + qid + 4]) };
                mma_tf32(acc[t], a, bb);
            }
        }
    }

    const int lm0 = m0 + grp, lm1 = lm0 + 8;
    const float inv0 = g_sinv[bh * cNL + l0 + lm0];
    const float inv1 = g_sinv[bh * cNL + l0 + lm1];
    __syncthreads();
#pragma unroll
    for (int t = 0; t < 4; t++) {
        const int c = n0 + t * 8 + 2 * qid;
        As[lm0][c]     = acc[t][0] * inv0;
        As[lm0][c + 1] = acc[t][1] * inv0;
        As[lm1][c]     = acc[t][2] * inv1;
        As[lm1][c + 1] = acc[t][3] * inv1;
    }
    __syncthreads();
    for (int i = tid; i < 1024; i += 256) {
        int l = i >> 4, c4 = (i & 15) * 4;
        *(float4*)&g_l3h[((size_t)(b * cNL) + l0 + l) * 512 + h * 64 + c4] =
            *(float4*)&As[l][c4];
    }
}

// =====================================================================
// atv (tf32 MMA): p3h[b,p,h*64+d] = sum_l e[l,p] * (L2t[d,l] * sinv[l])
// Flat smem buffer; output staged in two 64-row halves for coalesced writes.
// =====================================================================
__global__ __launch_bounds__(256) void atv_mma() {
    __shared__ float SB[128 * 33 + 64 * 33];    // As [128][33] | Bs [64][33]
#define ATV_A(p_, l_) SB[(p_) * 33 + (l_)]
#define ATV_B(d_, k_) SB[128 * 33 + (d_) * 33 + (k_)]
#define ATV_S(p_, c_) SB[(p_) * 68 + (c_)]     // stage [64][68], overlays As/Bs
    const int bh = blockIdx.y, b = bh >> 3, h = bh & 7;
    const int p0 = blockIdx.x * 128;
    const int tid = threadIdx.x, wid = tid >> 5, lane = tid & 31, grp = lane >> 2, qid = lane & 3;
    const int m0 = wid * 16;
    const float* eb = g_att + (size_t)bh * cNL * cNP;
    const float* L2b = g_L2t + (size_t)bh * 64 * cNL;
    const float* sv = g_sinv + (size_t)bh * cNL;
    float acc[8][4] = {};

    for (int lt = 0; lt < 8; lt++) {
        const int lb = lt * 32;
        __syncthreads();
        for (int i = tid; i < 32 * 128; i += 256) {
            int r = i >> 7, c = i & 127;     // r = l local, c = p local
            ATV_A(c, r) = eb[(size_t)(lb + r) * cNP + p0 + c];
        }
        for (int i = tid; i < 64 * 32; i += 256) {
            int d = i >> 5, k = i & 31;
            ATV_B(d, k) = tf32f(L2b[(size_t)d * cNL + lb + k] * sv[lb + k]);
        }
        __syncthreads();
#pragma unroll
        for (int kk = 0; kk < 4; kk++) {
            const int k0 = kk * 8;
            uint32_t a[4] = { __float_as_uint(ATV_A(m0 + grp, k0 + qid)),
                              __float_as_uint(ATV_A(m0 + grp + 8, k0 + qid)),
                              __float_as_uint(ATV_A(m0 + grp, k0 + qid + 4)),
                              __float_as_uint(ATV_A(m0 + grp + 8, k0 + qid + 4)) };
#pragma unroll
            for (int t = 0; t < 8; t++) {
                uint32_t bb[2] = { __float_as_uint(ATV_B(t * 8 + grp, k0 + qid)),
                                   __float_as_uint(ATV_B(t * 8 + grp, k0 + qid + 4)) };
                mma_tf32(acc[t], a, bb);
            }
        }
    }

    // staged epilogue, two halves of 64 p-rows each
#pragma unroll
    for (int half = 0; half < 2; half++) {
        __syncthreads();
        if ((wid >> 2) == half) {
            const int pl0 = (m0 & 63) + grp, pl1 = pl0 + 8;
#pragma unroll
            for (int t = 0; t < 8; t++) {
                const int c = t * 8 + 2 * qid;
                ATV_S(pl0, c)     = acc[t][0];
                ATV_S(pl0, c + 1) = acc[t][1];
                ATV_S(pl1, c)     = acc[t][2];
                ATV_S(pl1, c + 1) = acc[t][3];
            }
        }
        __syncthreads();
        const int pg = p0 + half * 64;
        for (int i = tid; i < 1024; i += 256) {
            int pl = i >> 4, c4 = (i & 15) * 4;
            *(float4*)&g_p3h[((size_t)(b * cNP) + pg + pl) * 512 + h * 64 + c4] =
                *(float4*)&ATV_S(pl, c4);
        }
    }
#undef ATV_A
#undef ATV_B
#undef ATV_S
}

// =====================================================================
// fc1 (tf32 MMA): Y[row,d] = X[row,:512] @ W[512,64] + bias. Staged epilogue.
// =====================================================================
__global__ __launch_bounds__(256) void fc1_mma(const float* __restrict__ w,
                                               const float* __restrict__ bias, int which) {
    const float* X = which ? g_p3h : g_l3h;
    float* Y = which ? g_y1p : g_y1l;
    __shared__ float As[64][68];
    __shared__ float Bs[64][68];
    const int row0 = blockIdx.x * 64;
    const int tid = threadIdx.x, wid = tid >> 5, lane = tid & 31, grp = lane >> 2, qid = lane & 3;
    const int m0 = (wid & 3) * 16, n0 = (wid >> 2) * 32;
    float acc[4][4] = {};

    for (int kt = 0; kt < 8; kt++) {
        const int kb = kt * 64;
        __syncthreads();
        for (int i = tid; i < 64 * 64; i += 256) {
            int r = i >> 6, k = i & 63;
            As[r][k] = tf32f(X[(size_t)(row0 + r) * 512 + kb + k]);
        }
        for (int i = tid; i < 64 * 64; i += 256) {
            int k = i >> 6, n = i & 63;
            Bs[n][k] = tf32f(w[(size_t)(kb + k) * 64 + n]);
        }
        __syncthreads();
#pragma unroll
        for (int kk = 0; kk < 8; kk++) {
            const int k0 = kk * 8;
            uint32_t a[4] = { __float_as_uint(As[m0 + grp][k0 + qid]),
                              __float_as_uint(As[m0 + grp + 8][k0 + qid]),
                              __float_as_uint(As[m0 + grp][k0 + qid + 4]),
                              __float_as_uint(As[m0 + grp + 8][k0 + qid + 4]) };
#pragma unroll
            for (int t = 0; t < 4; t++) {
                uint32_t bb[2] = { __float_as_uint(Bs[n0 + t * 8 + grp][k0 + qid]),
                                   __float_as_uint(Bs[n0 + t * 8 + grp][k0 + qid + 4]) };
                mma_tf32(acc[t], a, bb);
            }
        }
    }

    __syncthreads();
    const int r0l = m0 + grp, r1l = r0l + 8;
#pragma unroll
    for (int t = 0; t < 4; t++) {
        const int c = n0 + t * 8 + 2 * qid;
        const float bv0 = bias[c], bv1 = bias[c + 1];
        As[r0l][c]     = acc[t][0] + bv0;
        As[r0l][c + 1] = acc[t][1] + bv1;
        As[r1l][c]     = acc[t][2] + bv0;
        As[r1l][c + 1] = acc[t][3] + bv1;
    }
    __syncthreads();
    for (int i = tid; i < 1024; i += 256) {
        int r = i >> 4, c4 = (i & 15) * 4;
        *(float4*)&Y[(size_t)(row0 + r) * 64 + c4] = *(float4*)&As[r][c4];
    }
}

// =====================================================================
// fc2 (fp32, fused concat): out = relu( [Y1, orig] @ W[128,64] + bias )
// (already float4 row-coalesced)
// =====================================================================
__global__ __launch_bounds__(256) void fc2_kernel(const float* __restrict__ orig,
                                                  const float* __restrict__ w,
                                                  const float* __restrict__ bias,
                                                  float* __restrict__ out,
                                                  int N, int which, int row_off) {
    const float* Y1 = which ? g_y1p : g_y1l;
    __shared__ float As[32][68];
    __shared__ float Bs[32][68];
    const int row0 = blockIdx.x * 64;
    const int tid = threadIdx.x, ty = tid >> 4, tx = tid & 15;
    float acc[4][4] = {};

    for (int k0 = 0; k0 < 128; k0 += 32) {
        const float* src = (k0 < 64) ? Y1 : orig;
        const int kb = k0 & 63;
        for (int i = tid; i < 64 * 32; i += 256) {
            int r = i >> 5, k = i & 31;
            As[k][r] = src[(size_t)(row0 + r) * 64 + kb + k];
        }
        for (int i = tid; i < 32 * 64; i += 256) {
            int k = i >> 6, c = i & 63;
            Bs[k][c] = w[(size_t)(k0 + k) * 64 + c];
        }
        __syncthreads();
#pragma unroll
        for (int k = 0; k < 32; k++) {
            float4 a4 = *(const float4*)&As[k][ty * 4];
            float4 b4 = *(const float4*)&Bs[k][tx * 4];
            float a[4] = {a4.x, a4.y, a4.z, a4.w};
            float bb[4] = {b4.x, b4.y, b4.z, b4.w};
#pragma unroll
            for (int i = 0; i < 4; i++)
#pragma unroll
                for (int j = 0; j < 4; j++) acc[i][j] = fmaf(a[i], bb[j], acc[i][j]);
        }
        __syncthreads();
    }

#pragma unroll
    for (int i = 0; i < 4; i++) {
        int row = row0 + ty * 4 + i;
        int b = row / N, n = row % N;
        float4 o;
        float* op = (float*)&o;
#pragma unroll
        for (int j = 0; j < 4; j++)
            op[j] = fmaxf(acc[i][j] + bias[tx * 4 + j], 0.0f);
        *(float4*)&out[((size_t)b * cNT + row_off + n) * 64 + tx * 4] = o;
    }
}

// =====================================================================
extern "C" void kernel_launch(void* const* d_in, const int* in_sizes, int n_in,
                              void* d_out, int out_size) {
    (void)in_sizes; (void)n_in; (void)out_size;
    const float* ligand = (const float*)d_in[0];
    const float* prot   = (const float*)d_in[1];
    const float* dist   = (const float*)d_in[2];
    const float* w_l1 = (const float*)d_in[3];
    const float* b_l1 = (const float*)d_in[4];
    const float* w_l2 = (const float*)d_in[5];
    const float* b_l2 = (const float*)d_in[6];
    const float* w_p1 = (const float*)d_in[7];
    const float* b_p1 = (const float*)d_in[8];
    const float* w_p2 = (const float*)d_in[9];
    const float* b_p2 = (const float*)d_in[10];
    const float* fc11_w = (const float*)d_in[11];
    const float* fc11_b = (const float*)d_in[12];
    const float* fc12_w = (const float*)d_in[13];
    const float* fc12_b = (const float*)d_in[14];
    const float* fc21_w = (const float*)d_in[15];
    const float* fc21_b = (const float*)d_in[16];
    const float* fc22_w = (const float*)d_in[17];
    const float* fc22_b = (const float*)d_in[18];
    float* out = (float*)d_out;

    // Projections (tf32). L1/P1 natural layout; L2/P2 transposed [d][n].
    proj_mma<<<dim3(cB * cNL / 64, cH), 256>>>(ligand, w_l1, b_l1, cNL, 0);
    proj_mma<<<dim3(cB * cNL / 64, cH), 256>>>(ligand, w_l2, b_l2, cNL, 1);
    proj_mma<<<dim3(cB * cNP / 64, cH), 256>>>(prot, w_p1, b_p1, cNP, 2);
    proj_mma<<<dim3(cB * cNP / 64, cH), 256>>>(prot, w_p2, b_p2, cNP, 3);

    // Fused energy + mask + stable softmax numerator (max pass + recompute pass)
    energy_mma<<<dim3(cNL / 64, cB * cH), 256>>>(dist);

    // Attention GEMMs with normalization folded in
    av_mma<<<dim3(cNL / 64, cB * cH), 256>>>();
    atv_mma<<<dim3(cNP / 128, cB * cH), 256>>>();

    // FC heads
    fc1_mma<<<cB * cNL / 64, 256>>>(fc11_w, fc11_b, 0);
    fc1_mma<<<cB * cNP / 64, 256>>>(fc21_w, fc21_b, 1);
    fc2_kernel<<<cB * cNL / 64, 256>>>(ligand, fc12_w, fc12_b, out, cNL, 0, 0);
    fc2_kernel<<<cB * cNP / 64, 256>>>(prot, fc22_w, fc22_b, out, cNP, 1, cNL);
}